// round 16
// baseline (speedup 1.0000x reference)
#include <cuda_runtime.h>

#define KD 512
#define QD 256
#define N_ROWS 262144

#define MAIN_BLOCKS 444
#define MAIN_THREADS 256
#define WARPS_PER_BLOCK (MAIN_THREADS / 32)
#define CHUNK 16
#define NGROUPS 37
#define GROUP_SIZE (MAIN_BLOCKS / NGROUPS)      // 12
#define SKIP_MARGIN 30.0f

// Scratch (static __device__ — zero-initialized at load; reset by final block each replay)
__device__ __align__(16) float g_q[KD];
__device__ float g_pm[MAIN_BLOCKS];
__device__ float g_pl[MAIN_BLOCKS];
__device__ __align__(16) float g_pacc[(size_t)MAIN_BLOCKS * KD];  // 0.91 MB
__device__ float g_gm[NGROUPS];
__device__ float g_gl[NGROUPS];
__device__ __align__(16) float g_gacc[NGROUPS * KD];              // 76 KB
__device__ unsigned g_row_ctr;
__device__ unsigned g_gdone[NGROUPS];
__device__ unsigned g_alldone;
__device__ unsigned g_smax;            // float-ordered encoding of global running max score

__device__ __forceinline__ float neg_inf() { return __int_as_float(0xff800000); }

// safe exp(a - b): returns 0 when a == -inf (avoids -inf - -inf = NaN)
__device__ __forceinline__ float expw(float a, float b) {
    return (a == neg_inf()) ? 0.f : __expf(a - b);
}

// order-preserving float <-> uint encoding (for atomicMax on floats incl. negatives)
__device__ __forceinline__ unsigned enc_f(float x) {
    unsigned u = __float_as_uint(x);
    return (u & 0x80000000u) ? ~u : (u | 0x80000000u);
}
__device__ __forceinline__ float dec_f(unsigned e) {
    unsigned u = (e & 0x80000000u) ? (e ^ 0x80000000u) : ~e;
    return __uint_as_float(u);
}
// NOTE: first call after load sees g_smax == 0 -> dec_f(0) == NaN, filtered by fmaxf below.
#define SMAX_INIT 0x007FFFFFu   // enc_f(-inf)

// ---------------- Kernel 1: q = W @ query + b (PDL primary) ----------------
__global__ __launch_bounds__(128)
void qproj_kernel(const float* __restrict__ query,
                  const float* __restrict__ W,
                  const float* __restrict__ b) {
    cudaTriggerProgrammaticLaunchCompletion();   // let attn_main start ramping now
    const int wid  = threadIdx.x >> 5;
    const int lane = threadIdx.x & 31;
    const int row  = blockIdx.x * 4 + wid;      // 128*4 = 512 rows

    const float4* w4 = reinterpret_cast<const float4*>(W + (size_t)row * QD);
    const float4* q4 = reinterpret_cast<const float4*>(query);
    const float4 wa = __ldg(&w4[lane]);
    const float4 wb = __ldg(&w4[lane + 32]);
    const float4 qa = __ldg(&q4[lane]);
    const float4 qb = __ldg(&q4[lane + 32]);

    float s = wa.x * qa.x + wa.y * qa.y + wa.z * qa.z + wa.w * qa.w
            + wb.x * qb.x + wb.y * qb.y + wb.z * qb.z + wb.w * qb.w;
    #pragma unroll
    for (int o = 16; o > 0; o >>= 1) s += __shfl_xor_sync(0xffffffffu, s, o);
    if (lane == 0) g_q[row] = s + b[row];
}

// ---------------- Kernel 2: streaming pass + group pre-reduce + fused finalize ----------------
__global__ __launch_bounds__(MAIN_THREADS, 3)
void attn_main(const float* __restrict__ key, const float* __restrict__ value,
               float* __restrict__ out) {
    __shared__ float s_m[WARPS_PER_BLOCK];
    __shared__ float s_l[WARPS_PER_BLOCK];
    __shared__ __align__(16) float s_acc[WARPS_PER_BLOCK][KD];   // 16 KB
    __shared__ float s_sc[WARPS_PER_BLOCK][CHUNK];               // 512 B: first-chunk scores
    __shared__ float s_fgm[NGROUPS];
    __shared__ float s_fgl[NGROUPS];
    __shared__ int s_last;

    const int lane = threadIdx.x & 31;
    const int wid  = threadIdx.x >> 5;
    const int tid  = threadIdx.x;

    // pre-sync work that doesn't need q (overlaps qproj under PDL)
    unsigned cur = 0u;
    if (lane == 0) cur = atomicAdd(&g_row_ctr, (unsigned)CHUNK);
    cur = __shfl_sync(0xffffffffu, cur, 0);

    cudaGridDependencySynchronize();   // q is ready past this point

    const float4* q4 = reinterpret_cast<const float4*>(g_q);
    const float4 q0 = q4[lane], q1 = q4[lane + 32], q2 = q4[lane + 64], q3 = q4[lane + 96];

    const float4* __restrict__ k4 = reinterpret_cast<const float4*>(key);
    const float4* __restrict__ v4 = reinterpret_cast<const float4*>(value);

    float4 a0 = make_float4(0.f, 0.f, 0.f, 0.f), a1 = a0, a2 = a0, a3 = a0;
    float m = neg_inf();
    float l = 0.f;
    float gm = neg_inf();   // best-known global max score (conservative lower bound)

    // ======== first chunk: phase A (score-only; full 16 rows guaranteed: 3552*16 < N) ========
    {
        #pragma unroll 4
        for (int i = 0; i < CHUNK; ++i) {
            const size_t base = (size_t)(cur + i) * (KD / 4) + lane;
            const float4 k0 = __ldcs(&k4[base]);
            const float4 k1 = __ldcs(&k4[base + 32]);
            const float4 k2 = __ldcs(&k4[base + 64]);
            const float4 k3 = __ldcs(&k4[base + 96]);
            float s;
            s  = k0.x * q0.x + k0.y * q0.y + k0.z * q0.z + k0.w * q0.w;
            s += k1.x * q1.x + k1.y * q1.y + k1.z * q1.z + k1.w * q1.w;
            s += k2.x * q2.x + k2.y * q2.y + k2.z * q2.z + k2.w * q2.w;
            s += k3.x * q3.x + k3.y * q3.y + k3.z * q3.z + k3.w * q3.w;
            #pragma unroll
            for (int o = 16; o > 0; o >>= 1) s += __shfl_xor_sync(0xffffffffu, s, o);
            if (lane == 0) s_sc[wid][i] = s;
            m = fmaxf(m, s);
        }
        __syncwarp();

        // publish local max, learn global max (NaN from first-call g_smax==0 filtered by fmaxf)
        float gm_new = gm;
        if (lane == 0) gm_new = fmaxf(gm, dec_f(atomicMax(&g_smax, enc_f(m))));
        gm = fmaxf(gm, __shfl_sync(0xffffffffu, gm_new, 0));

        // phase B: gated v gather for the first chunk
        const float thr = fmaxf(m, gm) - SKIP_MARGIN;
        #pragma unroll 4
        for (int i = 0; i < CHUNK; ++i) {
            const float s = s_sc[wid][i];
            if (s > thr) {
                const size_t base = (size_t)(cur + i) * (KD / 4) + lane;
                const float4 v0 = __ldcs(&v4[base]);
                const float4 v1 = __ldcs(&v4[base + 32]);
                const float4 v2 = __ldcs(&v4[base + 64]);
                const float4 v3 = __ldcs(&v4[base + 96]);
                const float w = __expf(s - m);
                l += w;
                a0.x += w * v0.x;  a0.y += w * v0.y;  a0.z += w * v0.z;  a0.w += w * v0.w;
                a1.x += w * v1.x;  a1.y += w * v1.y;  a1.z += w * v1.z;  a1.w += w * v1.w;
                a2.x += w * v2.x;  a2.y += w * v2.y;  a2.z += w * v2.z;  a2.w += w * v2.w;
                a3.x += w * v3.x;  a3.y += w * v3.y;  a3.z += w * v3.z;  a3.w += w * v3.w;
            }
        }
    }

    // grab next chunk and enter steady-state loop
    if (lane == 0) cur = atomicAdd(&g_row_ctr, (unsigned)CHUNK);
    cur = __shfl_sync(0xffffffffu, cur, 0);

    while (cur < (unsigned)N_ROWS) {
        unsigned nxt = 0u;
        float gm_new = gm;
        if (lane == 0) {
            nxt = atomicAdd(&g_row_ctr, (unsigned)CHUNK);       // issued early, latency hidden
            gm_new = fmaxf(gm, dec_f(atomicMax(&g_smax, enc_f(m))));
        }
        nxt = __shfl_sync(0xffffffffu, nxt, 0);
        gm = fmaxf(gm, __shfl_sync(0xffffffffu, gm_new, 0));

        float thresh = fmaxf(m, gm) - SKIP_MARGIN;

        const unsigned row_end = min(cur + (unsigned)CHUNK, (unsigned)N_ROWS);
        for (unsigned row = cur; row < row_end; ++row) {
            const size_t base = (size_t)row * (KD / 4) + lane;
            const float4 k0 = __ldcs(&k4[base]);
            const float4 k1 = __ldcs(&k4[base + 32]);
            const float4 k2 = __ldcs(&k4[base + 64]);
            const float4 k3 = __ldcs(&k4[base + 96]);

            float s;
            s  = k0.x * q0.x + k0.y * q0.y + k0.z * q0.z + k0.w * q0.w;
            s += k1.x * q1.x + k1.y * q1.y + k1.z * q1.z + k1.w * q1.w;
            s += k2.x * q2.x + k2.y * q2.y + k2.z * q2.z + k2.w * q2.w;
            s += k3.x * q3.x + k3.y * q3.y + k3.z * q3.z + k3.w * q3.w;
            #pragma unroll
            for (int o = 16; o > 0; o >>= 1) s += __shfl_xor_sync(0xffffffffu, s, o);

            if (s > thresh) {                       // warp-uniform branch
                const float4 v0 = __ldcs(&v4[base]);
                const float4 v1 = __ldcs(&v4[base + 32]);
                const float4 v2 = __ldcs(&v4[base + 64]);
                const float4 v3 = __ldcs(&v4[base + 96]);

                if (s > m) {
                    const float sc = (m == neg_inf()) ? 0.f : __expf(m - s);
                    m = s;
                    thresh = fmaxf(m, gm) - SKIP_MARGIN;
                    l = l * sc + 1.f;
                    a0.x = a0.x * sc + v0.x;  a0.y = a0.y * sc + v0.y;
                    a0.z = a0.z * sc + v0.z;  a0.w = a0.w * sc + v0.w;
                    a1.x = a1.x * sc + v1.x;  a1.y = a1.y * sc + v1.y;
                    a1.z = a1.z * sc + v1.z;  a1.w = a1.w * sc + v1.w;
                    a2.x = a2.x * sc + v2.x;  a2.y = a2.y * sc + v2.y;
                    a2.z = a2.z * sc + v2.z;  a2.w = a2.w * sc + v2.w;
                    a3.x = a3.x * sc + v3.x;  a3.y = a3.y * sc + v3.y;
                    a3.z = a3.z * sc + v3.z;  a3.w = a3.w * sc + v3.w;
                } else {
                    const float w = __expf(s - m);
                    l += w;
                    a0.x += w * v0.x;  a0.y += w * v0.y;  a0.z += w * v0.z;  a0.w += w * v0.w;
                    a1.x += w * v1.x;  a1.y += w * v1.y;  a1.z += w * v1.z;  a1.w += w * v1.w;
                    a2.x += w * v2.x;  a2.y += w * v2.y;  a2.z += w * v2.z;  a2.w += w * v2.w;
                    a3.x += w * v3.x;  a3.y += w * v3.y;  a3.z += w * v3.z;  a3.w += w * v3.w;
                }
            }
        }
        cur = nxt;
    }

    // ---- block-level reduce of 8 warp partials ----
    float4* sa = reinterpret_cast<float4*>(s_acc[wid]);
    sa[lane] = a0; sa[lane + 32] = a1; sa[lane + 64] = a2; sa[lane + 96] = a3;
    if (lane == 0) { s_m[wid] = m; s_l[wid] = l; }
    __syncthreads();

    float Mb = neg_inf();
    #pragma unroll
    for (int w = 0; w < WARPS_PER_BLOCK; ++w) Mb = fmaxf(Mb, s_m[w]);
    float c[WARPS_PER_BLOCK];
    #pragma unroll
    for (int w = 0; w < WARPS_PER_BLOCK; ++w) c[w] = expw(s_m[w], Mb);

    #pragma unroll
    for (int r = 0; r < 2; ++r) {
        const int d = tid + r * MAIN_THREADS;
        float acc = 0.f;
        #pragma unroll
        for (int w = 0; w < WARPS_PER_BLOCK; ++w) acc += c[w] * s_acc[w][d];
        g_pacc[(size_t)blockIdx.x * KD + d] = acc;
    }
    if (tid == 0) {
        float lb = 0.f;
        #pragma unroll
        for (int w = 0; w < WARPS_PER_BLOCK; ++w) lb += c[w] * s_l[w];
        g_pm[blockIdx.x] = Mb;
        g_pl[blockIdx.x] = lb;
    }
    __syncthreads();

    // ---- group ticket: last finisher of each 12-block group pre-reduces (overlaps stream) ----
    const int grp = blockIdx.x / GROUP_SIZE;
    if (tid == 0) {
        __threadfence();
        const unsigned d = atomicAdd(&g_gdone[grp], 1u);
        s_last = (d == GROUP_SIZE - 1u) ? 1 : 0;
    }
    __syncthreads();
    if (!s_last) return;

    const int b0 = grp * GROUP_SIZE;
    float gmx = neg_inf();
    #pragma unroll
    for (int bb = 0; bb < GROUP_SIZE; ++bb) gmx = fmaxf(gmx, __ldcg(&g_pm[b0 + bb]));
    float gc[GROUP_SIZE];
    #pragma unroll
    for (int bb = 0; bb < GROUP_SIZE; ++bb) gc[bb] = expw(__ldcg(&g_pm[b0 + bb]), gmx);

    #pragma unroll
    for (int r = 0; r < 2; ++r) {
        const int d = tid + r * MAIN_THREADS;
        float acc = 0.f;
        #pragma unroll
        for (int bb = 0; bb < GROUP_SIZE; ++bb)
            acc += gc[bb] * __ldcg(&g_pacc[(size_t)(b0 + bb) * KD + d]);
        g_gacc[grp * KD + d] = acc;
    }
    if (tid == 0) {
        float gl = 0.f;
        #pragma unroll
        for (int bb = 0; bb < GROUP_SIZE; ++bb) gl += gc[bb] * __ldcg(&g_pl[b0 + bb]);
        g_gm[grp] = gmx;
        g_gl[grp] = gl;
    }
    __syncthreads();

    // ---- global ticket over group-finishers: last one finalizes out + resets ----
    if (tid == 0) {
        __threadfence();
        const unsigned d = atomicAdd(&g_alldone, 1u);
        s_last = (d == NGROUPS - 1u) ? 1 : 0;
    }
    __syncthreads();
    if (!s_last) return;

    if (tid < NGROUPS) { s_fgm[tid] = __ldcg(&g_gm[tid]); s_fgl[tid] = __ldcg(&g_gl[tid]); }
    __syncthreads();

    float M = neg_inf();
    #pragma unroll
    for (int g = 0; g < NGROUPS; ++g) M = fmaxf(M, s_fgm[g]);
    float L = 0.f;
    #pragma unroll
    for (int g = 0; g < NGROUPS; ++g) L += expw(s_fgm[g], M) * s_fgl[g];
    const float invL = 1.f / L;

    #pragma unroll
    for (int r = 0; r < 2; ++r) {
        const int d = tid + r * MAIN_THREADS;
        float acc = 0.f;
        #pragma unroll
        for (int g = 0; g < NGROUPS; ++g)
            acc += expw(s_fgm[g], M) * __ldcg(&g_gacc[g * KD + d]);
        out[d] = acc * invL;
    }
    __syncthreads();

    // reset counters for the next graph replay
    if (tid == 0) { g_row_ctr = 0u; g_alldone = 0u; g_smax = SMAX_INIT; }
    if (tid < NGROUPS) g_gdone[tid] = 0u;
    __threadfence();
}

extern "C" void kernel_launch(void* const* d_in, const int* in_sizes, int n_in,
                              void* d_out, int out_size) {
    const float* query = (const float*)d_in[0];
    const float* key   = (const float*)d_in[1];
    const float* value = (const float*)d_in[2];
    const float* W     = (const float*)d_in[3];
    const float* b     = (const float*)d_in[4];
    float* out = (float*)d_out;

    qproj_kernel<<<128, 128>>>(query, W, b);

    cudaLaunchConfig_t cfg = {};
    cfg.gridDim  = dim3(MAIN_BLOCKS, 1, 1);
    cfg.blockDim = dim3(MAIN_THREADS, 1, 1);
    cudaLaunchAttribute attrs[1];
    attrs[0].id = cudaLaunchAttributeProgrammaticStreamSerialization;
    attrs[0].val.programmaticStreamSerializationAllowed = 1;
    cfg.attrs = attrs;
    cfg.numAttrs = 1;
    cudaLaunchKernelEx(&cfg, attn_main, key, value, out);
}